// round 1
// baseline (speedup 1.0000x reference)
#include <cuda_runtime.h>

// FlowNet-C correlation cost, K=1, MD=20, S1=1, S2=2, PAD=20
// A,B: [16,48,64,256] f32 (channels-last). Out: [16,48,64,441] f32.
// out[b,h,w, tj*21+ti] = (1/256) * sum_c A[b,h,w,c] * B[b, h+2tj-20, w+2ti-20, c]
// (zero when the shifted B index is out of bounds).

#define BATCH 16
#define HH    48
#define WW    64
#define CC    256
#define DISP  21

// smem layout (floats):
//   a_s: [2 h][64 w][272]   (256 channels stored as 4 chunks of 64 + 4-float pad)
//   b_s: [2 h][104 u][68]   (64-channel chunk + 4-float pad; u = w + dx + 20, halo zero-filled)
#define A_ROW_STRIDE 272
#define A_S_FLOATS   (2 * 64 * A_ROW_STRIDE)   // 34816
#define B_ROW_STRIDE 68
#define B_S_FLOATS   (2 * 104 * B_ROW_STRIDE)  // 14144
#define SMEM_BYTES   ((A_S_FLOATS + B_S_FLOATS) * 4)  // 195840

__global__ __launch_bounds__(384, 1)
void corr_kernel(const float* __restrict__ A,
                 const float* __restrict__ B,
                 float* __restrict__ O)
{
    extern __shared__ float smem[];
    float* a_s = smem;
    float* b_s = smem + A_S_FLOATS;

    const int tid = threadIdx.x;
    const int h0  = blockIdx.x * 2;   // 24 blocks cover H=48
    const int bb  = blockIdx.y;

    // ---- load A strip (2 rows, all 256 channels) into smem once ----
    // 2*64*64 = 8192 float4 elements
    for (int s = tid; s < 8192; s += 384) {
        int c4 = s & 63;            // float4 index within 256 channels
        int w  = (s >> 6) & 63;
        int h  = s >> 12;           // 0..1
        float4 v = *(const float4*)(A + (((size_t)(bb * HH + h0 + h) * WW + w) * CC) + c4 * 4);
        int cb  = c4 * 4;
        int pos = (h * 64 + w) * A_ROW_STRIDE + (cb >> 6) * 68 + (cb & 63);
        *(float4*)(a_s + pos) = v;
    }

    // ---- thread decomposition ----
    const int q      = tid & 3;          // channel quarter (16 of each 64-chunk)
    const int tile   = tid >> 2;         // 0..95
    const int hidx   = (tile >= 48) ? 1 : 0;
    const int t2     = tile - hidx * 48; // 0..47
    const int tislot = t2 >> 4;          // 0..2  -> ti = tislot*7 + k
    const int wslot  = t2 & 15;
    const int wbase  = ((wslot >> 1) << 3) + (wslot & 1);  // covers all 64 w via wbase + {0,2,4,6}
    const int ub     = wbase + 14 * tislot;                // b_s u base; u = ub + 2*(i+k), max 103

    const float* ap_base = a_s + (hidx * 64 + wbase) * A_ROW_STRIDE + q * 16;
    const float* bp_base = b_s + (hidx * 104 + ub) * B_ROW_STRIDE + q * 16;

    const float inv = 1.0f / 256.0f;

    for (int dyi = 0; dyi < DISP; ++dyi) {
        const int dy = 2 * dyi - 20;

        float acc[4][7];
        #pragma unroll
        for (int i = 0; i < 4; ++i)
            #pragma unroll
            for (int k = 0; k < 7; ++k) acc[i][k] = 0.0f;

        for (int ccb = 0; ccb < 4; ++ccb) {   // 64-channel chunks
            __syncthreads();
            // load B chunk: 2 rows x 104 u x 16 float4 = 3328 float4
            for (int s = tid; s < 3328; s += 384) {
                int c4 = s & 15;
                int u  = (s >> 4) % 104;
                int r  = s / 1664;           // 0..1
                int hb = h0 + r + dy;
                int wb = u - 20;
                float4 v = make_float4(0.f, 0.f, 0.f, 0.f);
                if ((unsigned)hb < (unsigned)HH && (unsigned)wb < (unsigned)WW)
                    v = *(const float4*)(B + ((size_t)(bb * HH + hb) * WW + wb) * CC + ccb * 64 + c4 * 4);
                *(float4*)(b_s + (r * 104 + u) * B_ROW_STRIDE + c4 * 4) = v;
            }
            __syncthreads();

            const float* ap = ap_base + ccb * 68;
            #pragma unroll
            for (int quad = 0; quad < 4; ++quad) {   // 4 channels per quad
                float4 a4[4], b4[10];
                #pragma unroll
                for (int i = 0; i < 4; ++i)
                    a4[i] = *(const float4*)(ap + (2 * i) * A_ROW_STRIDE + quad * 4);
                #pragma unroll
                for (int j = 0; j < 10; ++j)
                    b4[j] = *(const float4*)(bp_base + (2 * j) * B_ROW_STRIDE + quad * 4);
                #pragma unroll
                for (int i = 0; i < 4; ++i) {
                    #pragma unroll
                    for (int k = 0; k < 7; ++k) {
                        float4 bv = b4[i + k];
                        acc[i][k] += a4[i].x * bv.x;
                        acc[i][k] += a4[i].y * bv.y;
                        acc[i][k] += a4[i].z * bv.z;
                        acc[i][k] += a4[i].w * bv.w;
                    }
                }
            }
        }

        // ---- reduce the 4-way channel split (q lanes are adjacent) ----
        #pragma unroll
        for (int i = 0; i < 4; ++i) {
            #pragma unroll
            for (int k = 0; k < 7; ++k) {
                float v = acc[i][k];
                v += __shfl_xor_sync(0xffffffffu, v, 1);
                v += __shfl_xor_sync(0xffffffffu, v, 2);
                acc[i][k] = v;
            }
        }

        if (q == 0) {
            const int h = h0 + hidx;
            #pragma unroll
            for (int i = 0; i < 4; ++i) {
                const int w = wbase + 2 * i;
                float* op = O + ((size_t)((bb * HH + h) * WW + w)) * 441 + dyi * 21 + tislot * 7;
                #pragma unroll
                for (int k = 0; k < 7; ++k)
                    op[k] = acc[i][k] * inv;
            }
        }
    }
}

extern "C" void kernel_launch(void* const* d_in, const int* in_sizes, int n_in,
                              void* d_out, int out_size)
{
    const float* A = (const float*)d_in[0];
    const float* B = (const float*)d_in[1];
    float* O = (float*)d_out;

    static int configured = 0;
    if (!configured) {
        cudaFuncSetAttribute(corr_kernel,
                             cudaFuncAttributeMaxDynamicSharedMemorySize,
                             SMEM_BYTES);
        configured = 1;
    }

    dim3 grid(HH / 2, BATCH);
    corr_kernel<<<grid, 384, SMEM_BYTES>>>(A, B, O);
}

// round 3
// speedup vs baseline: 3.8617x; 3.8617x over previous
#include <cuda_runtime.h>
#include <cstdint>

// FlowNet-C correlation cost via warp-level bf16 mma.sync (sm_80+ path,
// compiles under compute_103 virtual arch; tcgen05 is unavailable here).
//
// out[b,h,w, tj*21+ti] = (1/256) * sum_c A[b,h,w,c] * B[b, h+2tj-20, w+2ti-20, c]
// A,B: [16,48,64,256] f32. Out: [16,48,64,441] f32.
//
// Parity split: u = w + 2ti - 20 has parity(u)==parity(w). Per (b,h,dy):
// two GEMMs D_p[32 w-half, 32 u-half] over K=256, p in {even,odd}.
// fp32 -> bf16 hi + bf16 residual lo; acc += Ahi*Bhi + Ahi*Blo + Alo*Bhi.

#define BATCH 16
#define HH 48
#define WW 64
#define CC 256
#define NDY 21

#define RS 264                         // padded bf16 row stride (528B: conflict-free ldmatrix)
#define PLANE_B (32 * RS * 2)          // 16896 B  (one parity plane)
#define COMP_B  (2 * PLANE_B)          // 33792 B  (hi or lo, both parities)
#define ROWSET_B (2 * COMP_B)          // 67584 B  (hi + lo)
#define NCHUNK  (ROWSET_B / 16)        // 4224 16B chunks

#define SM_B0 0
#define SM_B1 ROWSET_B
#define SM_A  (2 * ROWSET_B)           // 135168
#define SM_RED (SM_A + ROWSET_B)       // 202752
#define RED_STRIDE 34
#define RED_PL (32 * RED_STRIDE * 4)   // 4352 B per [parity][slot]
#define SM_TOTAL (SM_RED + 4 * RED_PL) // 220160

// B pre-converted to bf16 hi/lo in the exact smem rowset layout (flat copyable)
__device__ unsigned char g_B[(size_t)BATCH * HH * ROWSET_B];

// ---------------- helpers ----------------
__device__ __forceinline__ uint32_t smem_u32(const void* p) {
    uint32_t a;
    asm("{ .reg .u64 t; cvta.to.shared.u64 t, %1; cvt.u32.u64 %0, t; }"
        : "=r"(a) : "l"(p));
    return a;
}

// fp32 pair -> packed bf16x2 hi + bf16x2 lo residual. Lower 16 bits = x0.
__device__ __forceinline__ void cvt_split(float x0, float x1, uint32_t& hi, uint32_t& lo) {
    uint32_t h;
    asm("cvt.rn.bf16x2.f32 %0, %1, %2;" : "=r"(h) : "f"(x1), "f"(x0));
    float b0 = __uint_as_float(h << 16);
    float b1 = __uint_as_float(h & 0xFFFF0000u);
    uint32_t l;
    asm("cvt.rn.bf16x2.f32 %0, %1, %2;" : "=r"(l) : "f"(x1 - b1), "f"(x0 - b0));
    hi = h; lo = l;
}

__device__ __forceinline__ void ldmx4(uint32_t* r, uint32_t addr) {
    asm volatile("ldmatrix.sync.aligned.m8n8.x4.shared.b16 {%0,%1,%2,%3}, [%4];"
        : "=r"(r[0]), "=r"(r[1]), "=r"(r[2]), "=r"(r[3]) : "r"(addr));
}
__device__ __forceinline__ void ldmx2(uint32_t* r, uint32_t addr) {
    asm volatile("ldmatrix.sync.aligned.m8n8.x2.shared.b16 {%0,%1}, [%2];"
        : "=r"(r[0]), "=r"(r[1]) : "r"(addr));
}
__device__ __forceinline__ void mma_bf16(float* c, const uint32_t* a, const uint32_t* b) {
    asm volatile("mma.sync.aligned.m16n8k16.row.col.f32.bf16.bf16.f32 "
        "{%0,%1,%2,%3}, {%4,%5,%6,%7}, {%8,%9}, {%0,%1,%2,%3};"
        : "+f"(c[0]), "+f"(c[1]), "+f"(c[2]), "+f"(c[3])
        : "r"(a[0]), "r"(a[1]), "r"(a[2]), "r"(a[3]), "r"(b[0]), "r"(b[1]));
}
__device__ __forceinline__ void cpa16(uint32_t dst, const void* src) {
    asm volatile("cp.async.cg.shared.global [%0], [%1], 16;"
                 :: "r"(dst), "l"(src) : "memory");
}

__device__ __forceinline__ void red_store(float* rp, const float acc[2][4][4], int lane) {
    #pragma unroll
    for (int mt = 0; mt < 2; ++mt)
        #pragma unroll
        for (int nt = 0; nt < 4; ++nt) {
            const int r0 = mt * 16 + (lane >> 2);
            const int c0 = nt * 8 + (lane & 3) * 2;
            *(float2*)(rp + r0 * RED_STRIDE + c0) =
                make_float2(acc[mt][nt][0], acc[mt][nt][1]);
            *(float2*)(rp + (r0 + 8) * RED_STRIDE + c0) =
                make_float2(acc[mt][nt][2], acc[mt][nt][3]);
        }
}
__device__ __forceinline__ void red_add(const float* rp, float acc[2][4][4], int lane) {
    #pragma unroll
    for (int mt = 0; mt < 2; ++mt)
        #pragma unroll
        for (int nt = 0; nt < 4; ++nt) {
            const int r0 = mt * 16 + (lane >> 2);
            const int c0 = nt * 8 + (lane & 3) * 2;
            float2 v0 = *(const float2*)(rp + r0 * RED_STRIDE + c0);
            float2 v1 = *(const float2*)(rp + (r0 + 8) * RED_STRIDE + c0);
            acc[mt][nt][0] += v0.x; acc[mt][nt][1] += v0.y;
            acc[mt][nt][2] += v1.x; acc[mt][nt][3] += v1.y;
        }
}

// ---------------- pre-pass: B fp32 -> bf16 hi/lo rowsets ----------------
__global__ void convert_b_kernel(const float* __restrict__ B) {
    const int bh = blockIdx.x;                 // (b*48 + h)
    const float4* src = (const float4*)(B + (size_t)bh * WW * CC);
    unsigned char* dst = g_B + (size_t)bh * ROWSET_B;
    #pragma unroll
    for (int j = 0; j < 16; ++j) {
        const int id = threadIdx.x + j * 256;  // float4 id over 64x256
        const int u = id >> 6, c4 = id & 63;
        float4 v = src[id];
        uint32_t h0, l0, h1, l1;
        cvt_split(v.x, v.y, h0, l0);
        cvt_split(v.z, v.w, h1, l1);
        const uint32_t off = (u & 1) * PLANE_B + (u >> 1) * (RS * 2) + c4 * 8;
        *(uint2*)(dst + off)          = make_uint2(h0, h1);
        *(uint2*)(dst + COMP_B + off) = make_uint2(l0, l1);
    }
}

// ---------------- main kernel ----------------
__global__ __launch_bounds__(256, 1)
void corr_mma_kernel(const float* __restrict__ A, float* __restrict__ O)
{
    extern __shared__ unsigned char smem[];
    const uint32_t sb = smem_u32(smem);
    const int tid  = threadIdx.x;
    const int lane = tid & 31;
    const int wid  = tid >> 5;
    const int p    = wid & 1;     // parity
    const int s    = wid >> 1;    // K-slice 0..3 (64 channels each)
    const int h    = blockIdx.x;
    const int bb   = blockIdx.y;

    // --- preload B(dy=0) into buf0 (flat cp.async; layout identical) ---
    {
        const int hb = h - 20;
        if ((unsigned)hb < (unsigned)HH) {
            const unsigned char* src = g_B + (size_t)(bb * HH + hb) * ROWSET_B;
            #pragma unroll
            for (int i = 0; i < 17; ++i) {
                const int idx = i * 256 + tid;
                if (idx < NCHUNK) cpa16(sb + SM_B0 + idx * 16, src + idx * 16);
            }
        }
        asm volatile("cp.async.commit_group;" ::: "memory");
    }

    // --- stage A row h -> bf16 hi/lo rowset in smem ---
    {
        const float4* asrc = (const float4*)(A + (size_t)(bb * HH + h) * WW * CC);
        #pragma unroll
        for (int j = 0; j < 16; ++j) {
            const int id = tid + j * 256;
            const int u = id >> 6, c4 = id & 63;
            float4 v = asrc[id];
            uint32_t h0, l0, h1, l1;
            cvt_split(v.x, v.y, h0, l0);
            cvt_split(v.z, v.w, h1, l1);
            const uint32_t off = (u & 1) * PLANE_B + (u >> 1) * (RS * 2) + c4 * 8;
            *(uint2*)(smem + SM_A + off)          = make_uint2(h0, h1);
            *(uint2*)(smem + SM_A + COMP_B + off) = make_uint2(l0, l1);
        }
    }
    asm volatile("cp.async.wait_group 0;" ::: "memory");
    __syncthreads();

    // --- A fragments -> registers for the whole dy loop ---
    uint32_t ahi[2][4][4], alo[2][4][4];
    {
        const uint32_t base_hi = sb + SM_A + p * PLANE_B;
        const uint32_t base_lo = base_hi + COMP_B;
        const int rrow = lane & 15;
        const int koff = (lane >> 4) * 16;   // +16B for k8..15 half
        #pragma unroll
        for (int mt = 0; mt < 2; ++mt)
            #pragma unroll
            for (int kt = 0; kt < 4; ++kt) {
                const uint32_t off =
                    (uint32_t)(mt * 16 + rrow) * (RS * 2) + (s * 64 + kt * 16) * 2 + koff;
                ldmx4(ahi[mt][kt], base_hi + off);
                ldmx4(alo[mt][kt], base_lo + off);
            }
    }

    const float inv = 1.0f / 256.0f;
    float* const redbase = (float*)(smem + SM_RED);

    for (int dyi = 0; dyi < NDY; ++dyi) {
        const int cur = dyi & 1;
        const int hbC = h + 2 * dyi - 20;
        const bool vC = (unsigned)hbC < (unsigned)HH;

        // prefetch next B row into the other buffer
        if (dyi < NDY - 1) {
            const int hbN = hbC + 2;
            if ((unsigned)hbN < (unsigned)HH) {
                const unsigned char* src = g_B + (size_t)(bb * HH + hbN) * ROWSET_B;
                const uint32_t dstb = sb + (cur ? SM_B0 : SM_B1);
                #pragma unroll
                for (int i = 0; i < 17; ++i) {
                    const int idx = i * 256 + tid;
                    if (idx < NCHUNK) cpa16(dstb + idx * 16, src + idx * 16);
                }
            }
        }
        asm volatile("cp.async.commit_group;" ::: "memory");

        float acc[2][4][4];
        #pragma unroll
        for (int mt = 0; mt < 2; ++mt)
            #pragma unroll
            for (int nt = 0; nt < 4; ++nt)
                #pragma unroll
                for (int r = 0; r < 4; ++r) acc[mt][nt][r] = 0.0f;

        if (vC) {
            const uint32_t bbh = sb + (cur ? SM_B1 : SM_B0) + p * PLANE_B;
            const uint32_t bbl = bbh + COMP_B;
            const int brow  = lane & 7;
            const int bkoff = ((lane >> 3) & 1) * 16;
            #pragma unroll
            for (int kt = 0; kt < 4; ++kt) {
                uint32_t bhi[4][2], blo[4][2];
                #pragma unroll
                for (int nt = 0; nt < 4; ++nt) {
                    const uint32_t off =
                        (uint32_t)(nt * 8 + brow) * (RS * 2) + (s * 64 + kt * 16) * 2 + bkoff;
                    ldmx2(bhi[nt], bbh + off);
                    ldmx2(blo[nt], bbl + off);
                }
                #pragma unroll
                for (int mt = 0; mt < 2; ++mt)
                    #pragma unroll
                    for (int nt = 0; nt < 4; ++nt) {
                        mma_bf16(acc[mt][nt], ahi[mt][kt], bhi[nt]);
                        mma_bf16(acc[mt][nt], ahi[mt][kt], blo[nt]);
                        mma_bf16(acc[mt][nt], alo[mt][kt], bhi[nt]);
                    }
            }
        }

        // --- cross-warp K-slice reduction (tree via smem) ---
        if (s >= 2) red_store(redbase + (p * 2 + (s - 2)) * (RED_PL / 4), acc, lane);
        __syncthreads();
        if (s < 2)  red_add(redbase + (p * 2 + s) * (RED_PL / 4), acc, lane);
        if (s == 1) red_store(redbase + (p * 2 + 1) * (RED_PL / 4), acc, lane);
        __syncthreads();
        if (s == 0) {
            red_add(redbase + (p * 2 + 1) * (RED_PL / 4), acc, lane);
            red_store(redbase + (p * 2 + 0) * (RED_PL / 4), acc, lane);
        }
        __syncthreads();

        // --- epilogue: band extract, write 64 w x 21 ti for tj=dyi ---
        {
            const int w = tid >> 2, g = tid & 3;
            const float* rp = redbase + ((w & 1) * 2) * (RED_PL / 4);
            float* op = O + ((size_t)(bb * HH + h) * WW + w) * 441 + dyi * 21;
            const int m = w >> 1;
            const int ticnt = (g == 3) ? 3 : 6;
            #pragma unroll
            for (int k = 0; k < 6; ++k) {
                if (k < ticnt) {
                    const int ti = g * 6 + k;
                    const int u = w + 2 * ti - 20;
                    float v = 0.0f;
                    if ((unsigned)u < (unsigned)WW)
                        v = rp[m * RED_STRIDE + (u >> 1)] * inv;
                    op[ti] = v;
                }
            }
        }

        asm volatile("cp.async.wait_group 0;" ::: "memory");
        __syncthreads();
    }
}

extern "C" void kernel_launch(void* const* d_in, const int* in_sizes, int n_in,
                              void* d_out, int out_size)
{
    const float* A = (const float*)d_in[0];
    const float* B = (const float*)d_in[1];
    float* O = (float*)d_out;

    static int configured = 0;
    if (!configured) {
        cudaFuncSetAttribute(corr_mma_kernel,
                             cudaFuncAttributeMaxDynamicSharedMemorySize,
                             SM_TOTAL);
        configured = 1;
    }

    convert_b_kernel<<<BATCH * HH, 256>>>(B);
    dim3 grid(HH, BATCH);
    corr_mma_kernel<<<grid, 256, SM_TOTAL>>>(A, O);
}

// round 5
// speedup vs baseline: 6.2803x; 1.6263x over previous
#include <cuda_runtime.h>
#include <cstdint>

// FlowNet-C correlation cost via warp-level bf16 mma.sync.
// out[b,h,w, tj*21+ti] = (1/256) * sum_c A[b,h,w,c] * B[b, h+2tj-20, w+2ti-20, c]
// A,B: [16,48,64,256] f32. Out: [16,48,64,441] f32.
//
// CTA = (h, b, parity). Parity split: u = w + 2ti - 20 keeps parity(w).
// Per dy: GEMM D[32 w-half, 32 u-half, K=256], fp32 via bf16 hi/lo 3-term split.
// 8 warps = M2 x N2 x K2; A fragments register-resident across the dy loop;
// K-halves fold in the epilogue (2 barriers per dy, no reduction tree).

#define BATCH 16
#define HH 48
#define WW 64
#define CC 256
#define NDY 21

#define RS 264                      // bf16 row stride (528B, conflict-free ldmatrix)
#define RSB (RS * 2)
#define PLANE 16896                 // 32 rows * 528B : one (parity,comp) plane
#define COMP_B (2 * PLANE)          // 33792: hi block in g_B (both parities)
#define ROWSET_B (2 * COMP_B)       // 67584 per (b,h)

// per-CTA smem
#define SM_B0 0                     // buf0: hi plane @0, lo plane @PLANE
#define SM_B1 (2 * PLANE)           // 33792
#define SM_A  (4 * PLANE)           // 67584: A hi @0, lo @PLANE
#define SM_D  (SM_A + 2 * PLANE)    // 101376
#define D_STRIDE 34                 // EVEN: keeps float2 smem stores 8B-aligned
#define D_SZ (32 * D_STRIDE * 4)    // 4352 per k-half
#define SM_TOTAL (SM_D + 2 * D_SZ)  // 110080  -> 2 CTAs/SM

// B pre-converted to bf16 hi/lo planes
__device__ unsigned char g_B[(size_t)BATCH * HH * ROWSET_B];

// ---------------- helpers ----------------
__device__ __forceinline__ uint32_t smem_u32(const void* p) {
    uint32_t a;
    asm("{ .reg .u64 t; cvta.to.shared.u64 t, %1; cvt.u32.u64 %0, t; }"
        : "=r"(a) : "l"(p));
    return a;
}
// fp32 pair -> packed bf16x2 hi + bf16x2 lo residual. Lower 16 bits = x0.
__device__ __forceinline__ void cvt_split(float x0, float x1, uint32_t& hi, uint32_t& lo) {
    uint32_t h;
    asm("cvt.rn.bf16x2.f32 %0, %1, %2;" : "=r"(h) : "f"(x1), "f"(x0));
    float b0 = __uint_as_float(h << 16);
    float b1 = __uint_as_float(h & 0xFFFF0000u);
    uint32_t l;
    asm("cvt.rn.bf16x2.f32 %0, %1, %2;" : "=r"(l) : "f"(x1 - b1), "f"(x0 - b0));
    hi = h; lo = l;
}
__device__ __forceinline__ void ldmx4(uint32_t* r, uint32_t addr) {
    asm volatile("ldmatrix.sync.aligned.m8n8.x4.shared.b16 {%0,%1,%2,%3}, [%4];"
        : "=r"(r[0]), "=r"(r[1]), "=r"(r[2]), "=r"(r[3]) : "r"(addr));
}
__device__ __forceinline__ void mma_bf16(float* c, const uint32_t* a, const uint32_t* b) {
    asm volatile("mma.sync.aligned.m16n8k16.row.col.f32.bf16.bf16.f32 "
        "{%0,%1,%2,%3}, {%4,%5,%6,%7}, {%8,%9}, {%0,%1,%2,%3};"
        : "+f"(c[0]), "+f"(c[1]), "+f"(c[2]), "+f"(c[3])
        : "r"(a[0]), "r"(a[1]), "r"(a[2]), "r"(a[3]), "r"(b[0]), "r"(b[1]));
}
__device__ __forceinline__ void cpa16(uint32_t dst, const void* src) {
    asm volatile("cp.async.cg.shared.global [%0], [%1], 16;"
                 :: "r"(dst), "l"(src) : "memory");
}

// ---------------- pre-pass: B fp32 -> bf16 hi/lo planes ----------------
__global__ void convert_b_kernel(const float* __restrict__ B) {
    const int bh = blockIdx.x;                 // b*48 + h
    const float4* src = (const float4*)(B + (size_t)bh * WW * CC);
    unsigned char* dst = g_B + (size_t)bh * ROWSET_B;
    #pragma unroll
    for (int j = 0; j < 16; ++j) {
        const int id = threadIdx.x + j * 256;  // float4 id over 64x256
        const int u = id >> 6, c4 = id & 63;
        float4 v = src[id];
        uint32_t h0, l0, h1, l1;
        cvt_split(v.x, v.y, h0, l0);
        cvt_split(v.z, v.w, h1, l1);
        const uint32_t off = (u & 1) * PLANE + (u >> 1) * RSB + c4 * 8;
        *(uint2*)(dst + off)          = make_uint2(h0, h1);
        *(uint2*)(dst + COMP_B + off) = make_uint2(l0, l1);
    }
}

// ---------------- main kernel ----------------
__global__ __launch_bounds__(256, 2)
void corr_mma_kernel(const float* __restrict__ A, float* __restrict__ O)
{
    extern __shared__ unsigned char smem[];
    const uint32_t sb = smem_u32(smem);
    const int tid  = threadIdx.x;
    const int lane = tid & 31;
    const int wid  = tid >> 5;
    const int kh = wid & 1;            // K half (128 ch)
    const int nh = (wid >> 1) & 1;     // N half (16 u')
    const int mh = (wid >> 2) & 1;     // M half (16 w')
    const int h  = blockIdx.x;
    const int bb = blockIdx.y;
    const int p  = blockIdx.z;         // parity

    // --- prefetch B(dy=0) into buf0 ---
    {
        const int hb = h - 20;
        if ((unsigned)hb < (unsigned)HH) {
            const unsigned char* srow = g_B + (size_t)(bb * HH + hb) * ROWSET_B + p * PLANE;
            for (int i = tid; i < 2112; i += 256)
                cpa16(sb + SM_B0 + i * 16,
                      (i < 1056) ? (srow + i * 16) : (srow + COMP_B + (i - 1056) * 16));
        }
        asm volatile("cp.async.commit_group;" ::: "memory");
    }

    // --- stage A row (this parity's 32 w) -> bf16 hi/lo planes in smem ---
    {
        const int w2 = tid >> 3, seg = tid & 7;    // 32 channels per seg
        const float4* asrc = (const float4*)(A
            + ((size_t)(bb * HH + h) * WW + 2 * w2 + p) * CC) + seg * 8;
        const uint32_t dsth = sb + SM_A + (uint32_t)w2 * RSB + seg * 64;
        #pragma unroll
        for (int j = 0; j < 8; ++j) {
            float4 v = asrc[j];
            uint32_t h0, l0, h1, l1;
            cvt_split(v.x, v.y, h0, l0);
            cvt_split(v.z, v.w, h1, l1);
            asm volatile("st.shared.v2.b32 [%0], {%1,%2};"
                         :: "r"(dsth + j * 8), "r"(h0), "r"(h1) : "memory");
            asm volatile("st.shared.v2.b32 [%0], {%1,%2};"
                         :: "r"(dsth + PLANE + j * 8), "r"(l0), "r"(l1) : "memory");
        }
    }
    asm volatile("cp.async.wait_group 0;" ::: "memory");
    __syncthreads();

    // --- A fragments -> registers for the whole dy loop ---
    uint32_t ahi[8][4], alo[8][4];
    {
        const uint32_t ab = sb + SM_A + (uint32_t)(mh * 16 + (lane & 15)) * RSB
                            + (lane >> 4) * 16 + kh * 256;
        #pragma unroll
        for (int kt = 0; kt < 8; ++kt) {
            ldmx4(ahi[kt], ab + kt * 32);
            ldmx4(alo[kt], ab + kt * 32 + PLANE);
        }
    }

    // B fragment address (x4: n16 x k16)
    const uint32_t boff = (uint32_t)(nh * 16 + ((lane >> 4) << 3) + (lane & 7)) * RSB
                          + ((lane >> 3) & 1) * 16 + kh * 256;
    const float inv = 1.0f / 256.0f;
    float* const Dmy = (float*)(smem + SM_D + kh * D_SZ);

    for (int dyi = 0; dyi < NDY; ++dyi) {
        const int cur = dyi & 1;

        // prefetch next dy's B planes into the other buffer
        if (dyi < NDY - 1) {
            const int hb = h + 2 * dyi - 18;
            if ((unsigned)hb < (unsigned)HH) {
                const unsigned char* srow =
                    g_B + (size_t)(bb * HH + hb) * ROWSET_B + p * PLANE;
                const uint32_t dst = sb + (cur ? SM_B0 : SM_B1);
                for (int i = tid; i < 2112; i += 256)
                    cpa16(dst + i * 16,
                          (i < 1056) ? (srow + i * 16) : (srow + COMP_B + (i - 1056) * 16));
            }
        }
        asm volatile("cp.async.commit_group;" ::: "memory");
        asm volatile("cp.async.wait_group 1;" ::: "memory");
        __syncthreads();                         // bar1: buf ready + D reusable

        float acc0[4] = {0.f, 0.f, 0.f, 0.f};
        float acc1[4] = {0.f, 0.f, 0.f, 0.f};
        const int hbC = h + 2 * dyi - 20;
        if ((unsigned)hbC < (unsigned)HH) {
            const uint32_t bbase = sb + (cur ? SM_B1 : SM_B0) + boff;
            #pragma unroll
            for (int kt = 0; kt < 8; ++kt) {
                uint32_t bh4[4], bl4[4];
                ldmx4(bh4, bbase + kt * 32);
                ldmx4(bl4, bbase + kt * 32 + PLANE);
                mma_bf16(acc0, ahi[kt], bh4);
                mma_bf16(acc0, ahi[kt], bl4);
                mma_bf16(acc0, alo[kt], bh4);
                mma_bf16(acc1, ahi[kt], bh4 + 2);
                mma_bf16(acc1, ahi[kt], bl4 + 2);
                mma_bf16(acc1, alo[kt], bh4 + 2);
            }
        }

        // store this warp's 16x32 tile piece into D[kh]
        {
            const int r = lane >> 2, c = nh * 16 + (lane & 3) * 2;
            float* d0 = Dmy + (mh * 16 + r) * D_STRIDE + c;
            *(float2*)(d0)                    = make_float2(acc0[0], acc0[1]);
            *(float2*)(d0 + 8 * D_STRIDE)     = make_float2(acc0[2], acc0[3]);
            *(float2*)(d0 + 8)                = make_float2(acc1[0], acc1[1]);
            *(float2*)(d0 + 8 * D_STRIDE + 8) = make_float2(acc1[2], acc1[3]);
        }
        __syncthreads();                         // bar2: D complete (all warps)

        // epilogue: fold k-halves, band extract, write 32 w x 21 ti
        {
            const float* D0 = (const float*)(smem + SM_D);
            const float* D1 = D0 + (D_SZ / 4);
            float* obase = O + ((size_t)(bb * HH + h) * WW) * 441 + (size_t)dyi * 21;
            for (int o = tid; o < 672; o += 256) {
                const int w2 = o / 21, ti = o - w2 * 21;
                const int u2 = w2 + ti - 10;
                float v = 0.0f;
                if ((unsigned)u2 < 32u)
                    v = (D0[w2 * D_STRIDE + u2] + D1[w2 * D_STRIDE + u2]) * inv;
                obase[(size_t)(2 * w2 + p) * 441 + ti] = v;
            }
        }
        // next iteration's bar1 protects D and B buffers
    }
}

extern "C" void kernel_launch(void* const* d_in, const int* in_sizes, int n_in,
                              void* d_out, int out_size)
{
    const float* A = (const float*)d_in[0];
    const float* B = (const float*)d_in[1];
    float* O = (float*)d_out;

    static int configured = 0;
    if (!configured) {
        cudaFuncSetAttribute(corr_mma_kernel,
                             cudaFuncAttributeMaxDynamicSharedMemorySize,
                             SM_TOTAL);
        configured = 1;
    }

    convert_b_kernel<<<BATCH * HH, 256>>>(B);
    dim3 grid(HH, BATCH, 2);
    corr_mma_kernel<<<grid, 256, SM_TOTAL>>>(A, O);
}

// round 6
// speedup vs baseline: 7.3005x; 1.1624x over previous
#include <cuda_runtime.h>
#include <cstdint>

// FlowNet-C correlation cost via warp-level fp16 mma.sync, 2-term split.
// out[b,h,w, tj*21+ti] = (1/256) * sum_c A[b,h,w,c] * B[b, h+2tj-20, w+2ti-20, c]
// A,B: [16,48,64,256] f32. Out: [16,48,64,441] f32.
//
// CTA = (h, b, parity). Per dy: GEMM D[32 w-half, 32 u-half, K=256].
// Precision: A = ahi + alo (exact fp16 2-term split), B ~ bhi (fp16).
// acc += ahi*bhi + alo*bhi = a*bhi; dropped a*blo ~ 2^-12 rel (<1e-3 gate).
// 8 warps = M2 x N2 x K2; A-hi fragments register-resident; A-lo re-ldmatrix'd
// per kt from smem (register cap for 3 CTAs/SM). K-halves fold in epilogue.

#define BATCH 16
#define HH 48
#define WW 64
#define CC 256
#define NDY 21

#define RS 264                      // fp16 row stride (528B, conflict-free ldmatrix)
#define RSB (RS * 2)
#define PLANE 16896                 // 32 rows * 528B
#define ROWSET_B (2 * PLANE)        // per (b,h): parity0 hi, parity1 hi

// per-CTA smem
#define SM_B0 0
#define SM_B1 PLANE                 // 16896
#define SM_A  (2 * PLANE)           // 33792 (A hi)
#define SM_ALO (3 * PLANE)          // 50688 (A lo)
#define SM_D  (4 * PLANE)           // 67584
#define D_STRIDE 34                 // even: float2 smem stores stay 8B aligned
#define D_SZ (32 * D_STRIDE * 4)    // 4352 per k-half
#define SM_TOTAL (SM_D + 2 * D_SZ)  // 76288 -> 3 CTAs/SM

// B pre-converted to fp16 hi planes
__device__ unsigned char g_B[(size_t)BATCH * HH * ROWSET_B];

// ---------------- helpers ----------------
__device__ __forceinline__ uint32_t smem_u32(const void* p) {
    uint32_t a;
    asm("{ .reg .u64 t; cvta.to.shared.u64 t, %1; cvt.u32.u64 %0, t; }"
        : "=r"(a) : "l"(p));
    return a;
}
// fp32 pair -> packed f16x2 (lower 16 bits = x0)
__device__ __forceinline__ uint32_t cvt_f16x2(float x0, float x1) {
    uint32_t h;
    asm("cvt.rn.f16x2.f32 %0, %1, %2;" : "=r"(h) : "f"(x1), "f"(x0));
    return h;
}
// fp32 pair -> fp16 hi + fp16 lo residual (exact 2-term split)
__device__ __forceinline__ void cvt_split_f16(float x0, float x1,
                                              uint32_t& hi, uint32_t& lo) {
    uint32_t h = cvt_f16x2(x0, x1);
    float h0, h1;
    asm("{ .reg .b16 l,u; mov.b32 {l,u}, %2; cvt.f32.f16 %0, l; cvt.f32.f16 %1, u; }"
        : "=f"(h0), "=f"(h1) : "r"(h));
    hi = h;
    lo = cvt_f16x2(x0 - h0, x1 - h1);
}
__device__ __forceinline__ void ldmx4(uint32_t* r, uint32_t addr) {
    asm volatile("ldmatrix.sync.aligned.m8n8.x4.shared.b16 {%0,%1,%2,%3}, [%4];"
        : "=r"(r[0]), "=r"(r[1]), "=r"(r[2]), "=r"(r[3]) : "r"(addr));
}
__device__ __forceinline__ void mma_f16(float* c, const uint32_t* a, const uint32_t* b) {
    asm volatile("mma.sync.aligned.m16n8k16.row.col.f32.f16.f16.f32 "
        "{%0,%1,%2,%3}, {%4,%5,%6,%7}, {%8,%9}, {%0,%1,%2,%3};"
        : "+f"(c[0]), "+f"(c[1]), "+f"(c[2]), "+f"(c[3])
        : "r"(a[0]), "r"(a[1]), "r"(a[2]), "r"(a[3]), "r"(b[0]), "r"(b[1]));
}
__device__ __forceinline__ void cpa16(uint32_t dst, const void* src) {
    asm volatile("cp.async.cg.shared.global [%0], [%1], 16;"
                 :: "r"(dst), "l"(src) : "memory");
}

// ---------------- pre-pass: B fp32 -> fp16 hi planes ----------------
__global__ void convert_b_kernel(const float* __restrict__ B) {
    const int bh = blockIdx.x;                 // b*48 + h
    const float4* src = (const float4*)(B + (size_t)bh * WW * CC);
    unsigned char* dst = g_B + (size_t)bh * ROWSET_B;
    #pragma unroll
    for (int j = 0; j < 16; ++j) {
        const int id = threadIdx.x + j * 256;  // float4 id over 64x256
        const int u = id >> 6, c4 = id & 63;
        float4 v = src[id];
        uint32_t h0 = cvt_f16x2(v.x, v.y);
        uint32_t h1 = cvt_f16x2(v.z, v.w);
        const uint32_t off = (u & 1) * PLANE + (u >> 1) * RSB + c4 * 8;
        *(uint2*)(dst + off) = make_uint2(h0, h1);
    }
}

// ---------------- main kernel ----------------
__global__ __launch_bounds__(256, 3)
void corr_mma_kernel(const float* __restrict__ A, float* __restrict__ O)
{
    extern __shared__ unsigned char smem[];
    const uint32_t sb = smem_u32(smem);
    const int tid  = threadIdx.x;
    const int lane = tid & 31;
    const int wid  = tid >> 5;
    const int kh = wid & 1;            // K half (128 ch)
    const int nh = (wid >> 1) & 1;     // N half (16 u')
    const int mh = (wid >> 2) & 1;     // M half (16 w')
    const int h  = blockIdx.x;
    const int bb = blockIdx.y;
    const int p  = blockIdx.z;         // parity

    // --- prefetch B(dy=0) into buf0 ---
    {
        const int hb = h - 20;
        if ((unsigned)hb < (unsigned)HH) {
            const unsigned char* srow =
                g_B + (size_t)(bb * HH + hb) * ROWSET_B + p * PLANE;
            for (int i = tid; i < 1056; i += 256)
                cpa16(sb + SM_B0 + i * 16, srow + i * 16);
        }
        asm volatile("cp.async.commit_group;" ::: "memory");
    }

    // --- stage A row (this parity's 32 w) -> fp16 hi/lo planes in smem ---
    {
        const int w2 = tid >> 3, seg = tid & 7;    // 32 channels per seg
        const float4* asrc = (const float4*)(A
            + ((size_t)(bb * HH + h) * WW + 2 * w2 + p) * CC) + seg * 8;
        const uint32_t dsth = sb + SM_A + (uint32_t)w2 * RSB + seg * 64;
        #pragma unroll
        for (int j = 0; j < 8; ++j) {
            float4 v = asrc[j];
            uint32_t h0, l0, h1, l1;
            cvt_split_f16(v.x, v.y, h0, l0);
            cvt_split_f16(v.z, v.w, h1, l1);
            asm volatile("st.shared.v2.b32 [%0], {%1,%2};"
                         :: "r"(dsth + j * 8), "r"(h0), "r"(h1) : "memory");
            asm volatile("st.shared.v2.b32 [%0], {%1,%2};"
                         :: "r"(dsth + PLANE + j * 8), "r"(l0), "r"(l1) : "memory");
        }
    }
    asm volatile("cp.async.wait_group 0;" ::: "memory");
    __syncthreads();

    // --- A-hi fragments -> registers for the whole dy loop ---
    uint32_t ahi[8][4];
    const uint32_t ab = sb + SM_A + (uint32_t)(mh * 16 + (lane & 15)) * RSB
                        + (lane >> 4) * 16 + kh * 256;
    #pragma unroll
    for (int kt = 0; kt < 8; ++kt)
        ldmx4(ahi[kt], ab + kt * 32);
    const uint32_t abLo = ab + PLANE;   // A-lo fragment base (re-read per dy)

    // B fragment address (x4: n16 x k16)
    const uint32_t boff = (uint32_t)(nh * 16 + ((lane >> 4) << 3) + (lane & 7)) * RSB
                          + ((lane >> 3) & 1) * 16 + kh * 256;
    const float inv = 1.0f / 256.0f;
    float* const Dmy = (float*)(smem + SM_D + kh * D_SZ);

    for (int dyi = 0; dyi < NDY; ++dyi) {
        const int cur = dyi & 1;

        // prefetch next dy's B plane into the other buffer
        if (dyi < NDY - 1) {
            const int hb = h + 2 * dyi - 18;
            if ((unsigned)hb < (unsigned)HH) {
                const unsigned char* srow =
                    g_B + (size_t)(bb * HH + hb) * ROWSET_B + p * PLANE;
                const uint32_t dst = sb + (cur ? SM_B0 : SM_B1);
                for (int i = tid; i < 1056; i += 256)
                    cpa16(dst + i * 16, srow + i * 16);
            }
        }
        asm volatile("cp.async.commit_group;" ::: "memory");
        asm volatile("cp.async.wait_group 1;" ::: "memory");
        __syncthreads();                         // bar1: buf ready + D reusable

        float acc0[4] = {0.f, 0.f, 0.f, 0.f};
        float acc1[4] = {0.f, 0.f, 0.f, 0.f};
        const int hbC = h + 2 * dyi - 20;
        if ((unsigned)hbC < (unsigned)HH) {
            const uint32_t bbase = sb + (cur ? SM_B1 : SM_B0) + boff;
            #pragma unroll
            for (int kt = 0; kt < 8; ++kt) {
                uint32_t bh4[4], al4[4];
                ldmx4(bh4, bbase + kt * 32);
                ldmx4(al4, abLo + kt * 32);
                mma_f16(acc0, ahi[kt], bh4);
                mma_f16(acc0, al4,     bh4);
                mma_f16(acc1, ahi[kt], bh4 + 2);
                mma_f16(acc1, al4,     bh4 + 2);
            }
        }

        // store this warp's 16x32 tile piece into D[kh]
        {
            const int r = lane >> 2, c = nh * 16 + (lane & 3) * 2;
            float* d0 = Dmy + (mh * 16 + r) * D_STRIDE + c;
            *(float2*)(d0)                    = make_float2(acc0[0], acc0[1]);
            *(float2*)(d0 + 8 * D_STRIDE)     = make_float2(acc0[2], acc0[3]);
            *(float2*)(d0 + 8)                = make_float2(acc1[0], acc1[1]);
            *(float2*)(d0 + 8 * D_STRIDE + 8) = make_float2(acc1[2], acc1[3]);
        }
        __syncthreads();                         // bar2: D complete (all warps)

        // epilogue: fold k-halves, band extract, write 32 w x 21 ti
        {
            const float* D0 = (const float*)(smem + SM_D);
            const float* D1 = D0 + (D_SZ / 4);
            float* obase = O + ((size_t)(bb * HH + h) * WW) * 441 + (size_t)dyi * 21;
            for (int o = tid; o < 672; o += 256) {
                const int w2 = o / 21, ti = o - w2 * 21;
                const int u2 = w2 + ti - 10;
                float v = 0.0f;
                if ((unsigned)u2 < 32u)
                    v = (D0[w2 * D_STRIDE + u2] + D1[w2 * D_STRIDE + u2]) * inv;
                obase[(size_t)(2 * w2 + p) * 441 + ti] = v;
            }
        }
        // next iteration's bar1 protects D and B buffers
    }
}

extern "C" void kernel_launch(void* const* d_in, const int* in_sizes, int n_in,
                              void* d_out, int out_size)
{
    const float* A = (const float*)d_in[0];
    const float* B = (const float*)d_in[1];
    float* O = (float*)d_out;

    static int configured = 0;
    if (!configured) {
        cudaFuncSetAttribute(corr_mma_kernel,
                             cudaFuncAttributeMaxDynamicSharedMemorySize,
                             SM_TOTAL);
        configured = 1;
    }

    convert_b_kernel<<<BATCH * HH, 256>>>(B);
    dim3 grid(HH, BATCH, 2);
    corr_mma_kernel<<<grid, 256, SM_TOTAL>>>(A, O);
}

// round 7
// speedup vs baseline: 7.5863x; 1.0392x over previous
#include <cuda_runtime.h>
#include <cstdint>

// FlowNet-C correlation cost via warp-level fp16 mma.sync, 2-term split.
// out[b,h,w, tj*21+ti] = (1/256) * sum_c A[b,h,w,c] * B[b, h+2tj-20, w+2ti-20, c]
// A,B: [16,48,64,256] f32. Out: [16,48,64,441] f32.
//
// CTA = (h, b, parity). Per dy: GEMM D[32 w-half, 32 u-half, K=256].
// Precision: A = ahi + alo (exact fp16 2-term split), B ~ bhi (fp16).
// acc += ahi*bhi + alo*bhi = a*bhi; dropped a*blo ~ 2^-12 rel (<1e-3 gate).
// 8 warps = M2 x N2 x K2; BOTH A-hi and A-lo fragments register-resident
// across the dy loop (mainloop LDSM = B only). K-halves fold in epilogue.

#define BATCH 16
#define HH 48
#define WW 64
#define CC 256
#define NDY 21

#define RS 264                      // fp16 row stride (528B, conflict-free ldmatrix)
#define RSB (RS * 2)
#define PLANE 16896                 // 32 rows * 528B
#define ROWSET_B (2 * PLANE)        // per (b,h): parity0 hi, parity1 hi

// per-CTA smem
#define SM_B0 0
#define SM_B1 PLANE                 // 16896
#define SM_A  (2 * PLANE)           // 33792 (A hi)
#define SM_ALO (3 * PLANE)          // 50688 (A lo)
#define SM_D  (4 * PLANE)           // 67584
#define D_STRIDE 34                 // even: float2 smem stores stay 8B aligned
#define D_SZ (32 * D_STRIDE * 4)    // 4352 per k-half
#define SM_TOTAL (SM_D + 2 * D_SZ)  // 76288 -> 2 CTAs/SM (reg-limited)

// B pre-converted to fp16 hi planes
__device__ unsigned char g_B[(size_t)BATCH * HH * ROWSET_B];

// ---------------- helpers ----------------
__device__ __forceinline__ uint32_t smem_u32(const void* p) {
    uint32_t a;
    asm("{ .reg .u64 t; cvta.to.shared.u64 t, %1; cvt.u32.u64 %0, t; }"
        : "=r"(a) : "l"(p));
    return a;
}
// fp32 pair -> packed f16x2 (lower 16 bits = x0)
__device__ __forceinline__ uint32_t cvt_f16x2(float x0, float x1) {
    uint32_t h;
    asm("cvt.rn.f16x2.f32 %0, %1, %2;" : "=r"(h) : "f"(x1), "f"(x0));
    return h;
}
// fp32 pair -> fp16 hi + fp16 lo residual (exact 2-term split)
__device__ __forceinline__ void cvt_split_f16(float x0, float x1,
                                              uint32_t& hi, uint32_t& lo) {
    uint32_t h = cvt_f16x2(x0, x1);
    float h0, h1;
    asm("{ .reg .b16 l,u; mov.b32 {l,u}, %2; cvt.f32.f16 %0, l; cvt.f32.f16 %1, u; }"
        : "=f"(h0), "=f"(h1) : "r"(h));
    hi = h;
    lo = cvt_f16x2(x0 - h0, x1 - h1);
}
__device__ __forceinline__ void ldmx4(uint32_t* r, uint32_t addr) {
    asm volatile("ldmatrix.sync.aligned.m8n8.x4.shared.b16 {%0,%1,%2,%3}, [%4];"
        : "=r"(r[0]), "=r"(r[1]), "=r"(r[2]), "=r"(r[3]) : "r"(addr));
}
__device__ __forceinline__ void mma_f16(float* c, const uint32_t* a, const uint32_t* b) {
    asm volatile("mma.sync.aligned.m16n8k16.row.col.f32.f16.f16.f32 "
        "{%0,%1,%2,%3}, {%4,%5,%6,%7}, {%8,%9}, {%0,%1,%2,%3};"
        : "+f"(c[0]), "+f"(c[1]), "+f"(c[2]), "+f"(c[3])
        : "r"(a[0]), "r"(a[1]), "r"(a[2]), "r"(a[3]), "r"(b[0]), "r"(b[1]));
}
__device__ __forceinline__ void cpa16(uint32_t dst, const void* src) {
    asm volatile("cp.async.cg.shared.global [%0], [%1], 16;"
                 :: "r"(dst), "l"(src) : "memory");
}

// ---------------- pre-pass: B fp32 -> fp16 hi planes ----------------
__global__ void convert_b_kernel(const float* __restrict__ B) {
    const int bh = blockIdx.x;                 // b*48 + h
    const float4* src = (const float4*)(B + (size_t)bh * WW * CC);
    unsigned char* dst = g_B + (size_t)bh * ROWSET_B;
    #pragma unroll
    for (int j = 0; j < 16; ++j) {
        const int id = threadIdx.x + j * 256;  // float4 id over 64x256
        const int u = id >> 6, c4 = id & 63;
        float4 v = src[id];
        uint32_t h0 = cvt_f16x2(v.x, v.y);
        uint32_t h1 = cvt_f16x2(v.z, v.w);
        const uint32_t off = (u & 1) * PLANE + (u >> 1) * RSB + c4 * 8;
        *(uint2*)(dst + off) = make_uint2(h0, h1);
    }
}

// ---------------- main kernel ----------------
__global__ __launch_bounds__(256, 2)
void corr_mma_kernel(const float* __restrict__ A, float* __restrict__ O)
{
    extern __shared__ unsigned char smem[];
    const uint32_t sb = smem_u32(smem);
    const int tid  = threadIdx.x;
    const int lane = tid & 31;
    const int wid  = tid >> 5;
    const int kh = wid & 1;            // K half (128 ch)
    const int nh = (wid >> 1) & 1;     // N half (16 u')
    const int mh = (wid >> 2) & 1;     // M half (16 w')
    const int h  = blockIdx.x;
    const int bb = blockIdx.y;
    const int p  = blockIdx.z;         // parity

    // --- prefetch B(dy=0) into buf0 ---
    {
        const int hb = h - 20;
        if ((unsigned)hb < (unsigned)HH) {
            const unsigned char* srow =
                g_B + (size_t)(bb * HH + hb) * ROWSET_B + p * PLANE;
            for (int i = tid; i < 1056; i += 256)
                cpa16(sb + SM_B0 + i * 16, srow + i * 16);
        }
        asm volatile("cp.async.commit_group;" ::: "memory");
    }

    // --- stage A row (this parity's 32 w) -> fp16 hi/lo planes in smem ---
    {
        const int w2 = tid >> 3, seg = tid & 7;    // 32 channels per seg
        const float4* asrc = (const float4*)(A
            + ((size_t)(bb * HH + h) * WW + 2 * w2 + p) * CC) + seg * 8;
        const uint32_t dsth = sb + SM_A + (uint32_t)w2 * RSB + seg * 64;
        #pragma unroll
        for (int j = 0; j < 8; ++j) {
            float4 v = asrc[j];
            uint32_t h0, l0, h1, l1;
            cvt_split_f16(v.x, v.y, h0, l0);
            cvt_split_f16(v.z, v.w, h1, l1);
            asm volatile("st.shared.v2.b32 [%0], {%1,%2};"
                         :: "r"(dsth + j * 8), "r"(h0), "r"(h1) : "memory");
            asm volatile("st.shared.v2.b32 [%0], {%1,%2};"
                         :: "r"(dsth + PLANE + j * 8), "r"(l0), "r"(l1) : "memory");
        }
    }
    asm volatile("cp.async.wait_group 0;" ::: "memory");
    __syncthreads();

    // --- A-hi AND A-lo fragments -> registers for the whole dy loop ---
    uint32_t ahi[8][4], alo[8][4];
    {
        const uint32_t ab = sb + SM_A + (uint32_t)(mh * 16 + (lane & 15)) * RSB
                            + (lane >> 4) * 16 + kh * 256;
        #pragma unroll
        for (int kt = 0; kt < 8; ++kt) {
            ldmx4(ahi[kt], ab + kt * 32);
            ldmx4(alo[kt], ab + kt * 32 + PLANE);
        }
    }

    // B fragment address (x4: n16 x k16)
    const uint32_t boff = (uint32_t)(nh * 16 + ((lane >> 4) << 3) + (lane & 7)) * RSB
                          + ((lane >> 3) & 1) * 16 + kh * 256;
    const float inv = 1.0f / 256.0f;
    float* const Dmy = (float*)(smem + SM_D + kh * D_SZ);

    for (int dyi = 0; dyi < NDY; ++dyi) {
        const int cur = dyi & 1;

        // prefetch next dy's B plane into the other buffer
        if (dyi < NDY - 1) {
            const int hb = h + 2 * dyi - 18;
            if ((unsigned)hb < (unsigned)HH) {
                const unsigned char* srow =
                    g_B + (size_t)(bb * HH + hb) * ROWSET_B + p * PLANE;
                const uint32_t dst = sb + (cur ? SM_B0 : SM_B1);
                for (int i = tid; i < 1056; i += 256)
                    cpa16(dst + i * 16, srow + i * 16);
            }
        }
        asm volatile("cp.async.commit_group;" ::: "memory");
        asm volatile("cp.async.wait_group 1;" ::: "memory");
        __syncthreads();                         // bar1: buf ready + D reusable

        float acc0[4] = {0.f, 0.f, 0.f, 0.f};
        float acc1[4] = {0.f, 0.f, 0.f, 0.f};
        const int hbC = h + 2 * dyi - 20;
        if ((unsigned)hbC < (unsigned)HH) {
            const uint32_t bbase = sb + (cur ? SM_B1 : SM_B0) + boff;
            #pragma unroll
            for (int kt = 0; kt < 8; ++kt) {
                uint32_t bh4[4];
                ldmx4(bh4, bbase + kt * 32);
                mma_f16(acc0, ahi[kt], bh4);
                mma_f16(acc0, alo[kt], bh4);
                mma_f16(acc1, ahi[kt], bh4 + 2);
                mma_f16(acc1, alo[kt], bh4 + 2);
            }
        }

        // store this warp's 16x32 tile piece into D[kh]
        {
            const int r = lane >> 2, c = nh * 16 + (lane & 3) * 2;
            float* d0 = Dmy + (mh * 16 + r) * D_STRIDE + c;
            *(float2*)(d0)                    = make_float2(acc0[0], acc0[1]);
            *(float2*)(d0 + 8 * D_STRIDE)     = make_float2(acc0[2], acc0[3]);
            *(float2*)(d0 + 8)                = make_float2(acc1[0], acc1[1]);
            *(float2*)(d0 + 8 * D_STRIDE + 8) = make_float2(acc1[2], acc1[3]);
        }
        __syncthreads();                         // bar2: D complete (all warps)

        // epilogue: fold k-halves, band extract, write 32 w x 21 ti
        {
            const float* D0 = (const float*)(smem + SM_D);
            const float* D1 = D0 + (D_SZ / 4);
            float* obase = O + ((size_t)(bb * HH + h) * WW) * 441 + (size_t)dyi * 21;
            for (int o = tid; o < 672; o += 256) {
                const int w2 = o / 21, ti = o - w2 * 21;
                const int u2 = w2 + ti - 10;
                float v = 0.0f;
                if ((unsigned)u2 < 32u)
                    v = (D0[w2 * D_STRIDE + u2] + D1[w2 * D_STRIDE + u2]) * inv;
                obase[(size_t)(2 * w2 + p) * 441 + ti] = v;
            }
        }
        // next iteration's bar1 protects D and B buffers
    }
}

extern "C" void kernel_launch(void* const* d_in, const int* in_sizes, int n_in,
                              void* d_out, int out_size)
{
    const float* A = (const float*)d_in[0];
    const float* B = (const float*)d_in[1];
    float* O = (float*)d_out;

    static int configured = 0;
    if (!configured) {
        cudaFuncSetAttribute(corr_mma_kernel,
                             cudaFuncAttributeMaxDynamicSharedMemorySize,
                             SM_TOTAL);
        configured = 1;
    }

    convert_b_kernel<<<BATCH * HH, 256>>>(B);
    dim3 grid(HH, BATCH, 2);
    corr_mma_kernel<<<grid, 256, SM_TOTAL>>>(A, O);
}

// round 8
// speedup vs baseline: 8.2056x; 1.0816x over previous
#include <cuda_runtime.h>
#include <cstdint>

// FlowNet-C correlation cost via warp-level fp16 mma.sync, 2-term split.
// out[b,h,w, tj*21+ti] = (1/256) * sum_c A[b,h,w,c] * B[b, h+2tj-20, w+2ti-20, c]
// A,B: [16,48,64,256] f32. Out: [16,48,64,441] f32.
//
// CTA = (h, b, parity). Per dy: GEMM D[32 w-half, 32 u-half, K=256].
// Precision: A = ahi + alo (exact fp16 2-term split), B ~ bhi (fp16).
// 8 warps = M2 x N2 x K2; A hi/lo fragments register-resident.
// TWO dy per mainloop iteration: one barrier pair / cp wait / epilogue per
// 256 HMMAs. B ring = 4 planes (A staging planes recycled after prologue).

#define BATCH 16
#define HH 48
#define WW 64
#define CC 256
#define NDY 21

#define RS 264                      // fp16 row stride (528B, conflict-free ldmatrix)
#define RSB (RS * 2)
#define PLANE 16896                 // 32 rows * 528B
#define ROWSET_B (2 * PLANE)        // per (b,h): parity0 hi, parity1 hi

// per-CTA smem: 4-plane B ring (planes 2,3 double as A hi/lo staging in prologue)
#define SM_D (4 * PLANE)            // 67584
#define D_STRIDE 34                 // even: float2 smem stores stay 8B aligned
#define D_SZ (32 * D_STRIDE * 4)    // 4352 per (dyslot, khalf)
#define SM_TOTAL (SM_D + 4 * D_SZ)  // 84992 -> 2 CTAs/SM

// B pre-converted to fp16 hi planes
__device__ unsigned char g_B[(size_t)BATCH * HH * ROWSET_B];

// ---------------- helpers ----------------
__device__ __forceinline__ uint32_t smem_u32(const void* p) {
    uint32_t a;
    asm("{ .reg .u64 t; cvta.to.shared.u64 t, %1; cvt.u32.u64 %0, t; }"
        : "=r"(a) : "l"(p));
    return a;
}
__device__ __forceinline__ uint32_t cvt_f16x2(float x0, float x1) {
    uint32_t h;
    asm("cvt.rn.f16x2.f32 %0, %1, %2;" : "=r"(h) : "f"(x1), "f"(x0));
    return h;
}
// fp32 pair -> fp16 hi + fp16 lo residual (exact 2-term split)
__device__ __forceinline__ void cvt_split_f16(float x0, float x1,
                                              uint32_t& hi, uint32_t& lo) {
    uint32_t h = cvt_f16x2(x0, x1);
    float h0, h1;
    asm("{ .reg .b16 l,u; mov.b32 {l,u}, %2; cvt.f32.f16 %0, l; cvt.f32.f16 %1, u; }"
        : "=f"(h0), "=f"(h1) : "r"(h));
    hi = h;
    lo = cvt_f16x2(x0 - h0, x1 - h1);
}
__device__ __forceinline__ void ldmx4(uint32_t* r, uint32_t addr) {
    asm volatile("ldmatrix.sync.aligned.m8n8.x4.shared.b16 {%0,%1,%2,%3}, [%4];"
        : "=r"(r[0]), "=r"(r[1]), "=r"(r[2]), "=r"(r[3]) : "r"(addr));
}
__device__ __forceinline__ void mma_f16(float* c, const uint32_t* a, const uint32_t* b) {
    asm volatile("mma.sync.aligned.m16n8k16.row.col.f32.f16.f16.f32 "
        "{%0,%1,%2,%3}, {%4,%5,%6,%7}, {%8,%9}, {%0,%1,%2,%3};"
        : "+f"(c[0]), "+f"(c[1]), "+f"(c[2]), "+f"(c[3])
        : "r"(a[0]), "r"(a[1]), "r"(a[2]), "r"(a[3]), "r"(b[0]), "r"(b[1]));
}
__device__ __forceinline__ void cpa16(uint32_t dst, const void* src) {
    asm volatile("cp.async.cg.shared.global [%0], [%1], 16;"
                 :: "r"(dst), "l"(src) : "memory");
}
// fill one 16896B plane: 1056 chunks = 4*256 + 32, fully unrolled
__device__ __forceinline__ void fill_plane(uint32_t dst, const unsigned char* srow, int tid) {
    #pragma unroll
    for (int j = 0; j < 4; ++j)
        cpa16(dst + (uint32_t)(tid + j * 256) * 16, srow + (size_t)(tid + j * 256) * 16);
    if (tid < 32)
        cpa16(dst + (uint32_t)(tid + 1024) * 16, srow + (size_t)(tid + 1024) * 16);
}

// ---------------- pre-pass: B fp32 -> fp16 hi planes ----------------
__global__ void convert_b_kernel(const float* __restrict__ B) {
    const int bh = blockIdx.x;                 // b*48 + h
    const float4* src = (const float4*)(B + (size_t)bh * WW * CC);
    unsigned char* dst = g_B + (size_t)bh * ROWSET_B;
    #pragma unroll
    for (int j = 0; j < 16; ++j) {
        const int id = threadIdx.x + j * 256;  // float4 id over 64x256
        const int u = id >> 6, c4 = id & 63;
        float4 v = src[id];
        uint32_t h0 = cvt_f16x2(v.x, v.y);
        uint32_t h1 = cvt_f16x2(v.z, v.w);
        const uint32_t off = (u & 1) * PLANE + (u >> 1) * RSB + c4 * 8;
        *(uint2*)(dst + off) = make_uint2(h0, h1);
    }
}

// ---------------- main kernel ----------------
__global__ __launch_bounds__(256, 2)
void corr_mma_kernel(const float* __restrict__ A, float* __restrict__ O)
{
    extern __shared__ unsigned char smem[];
    const uint32_t sb = smem_u32(smem);
    const int tid  = threadIdx.x;
    const int lane = tid & 31;
    const int wid  = tid >> 5;
    const int kh = wid & 1;            // K half (128 ch)
    const int nh = (wid >> 1) & 1;     // N half (16 u')
    const int mh = (wid >> 2) & 1;     // M half (16 w')
    const int h  = blockIdx.x;
    const int bb = blockIdx.y;
    const int p  = blockIdx.z;         // parity

    const unsigned char* const browset = g_B + (size_t)(bb * HH) * ROWSET_B + p * PLANE;

    // --- prologue prefetch: B(dy0)->plane0, B(dy1)->plane1 ---
    #pragma unroll
    for (int f = 0; f < 2; ++f) {
        const int hb = h + 2 * f - 20;
        if ((unsigned)hb < (unsigned)HH)
            fill_plane(sb + (uint32_t)f * PLANE, browset + (size_t)hb * ROWSET_B, tid);
        asm volatile("cp.async.commit_group;" ::: "memory");
    }

    // --- stage A row (this parity's 32 w) -> fp16 hi/lo into planes 2,3 ---
    {
        const int w2 = tid >> 3, seg = tid & 7;    // 32 channels per seg
        const float4* asrc = (const float4*)(A
            + ((size_t)(bb * HH + h) * WW + 2 * w2 + p) * CC) + seg * 8;
        const uint32_t dsth = sb + 2 * PLANE + (uint32_t)w2 * RSB + seg * 64;
        #pragma unroll
        for (int j = 0; j < 8; ++j) {
            float4 v = asrc[j];
            uint32_t h0, l0, h1, l1;
            cvt_split_f16(v.x, v.y, h0, l0);
            cvt_split_f16(v.z, v.w, h1, l1);
            asm volatile("st.shared.v2.b32 [%0], {%1,%2};"
                         :: "r"(dsth + j * 8), "r"(h0), "r"(h1) : "memory");
            asm volatile("st.shared.v2.b32 [%0], {%1,%2};"
                         :: "r"(dsth + PLANE + j * 8), "r"(l0), "r"(l1) : "memory");
        }
    }
    __syncthreads();

    // --- A hi/lo fragments -> registers for the whole dy loop ---
    uint32_t ahi[8][4], alo[8][4];
    {
        const uint32_t ab = sb + 2 * PLANE + (uint32_t)(mh * 16 + (lane & 15)) * RSB
                            + (lane >> 4) * 16 + kh * 256;
        #pragma unroll
        for (int kt = 0; kt < 8; ++kt) {
            ldmx4(ahi[kt], ab + kt * 32);
            ldmx4(alo[kt], ab + kt * 32 + PLANE);
        }
    }
    __syncthreads();   // planes 2,3 free for B ring after this

    // B fragment offset within a plane (x4: n16 x k16)
    const uint32_t boff = (uint32_t)(nh * 16 + ((lane >> 4) << 3) + (lane & 7)) * RSB
                          + ((lane >> 3) & 1) * 16 + kh * 256;
    const float inv = 1.0f / 256.0f;
    float* const DmyA = (float*)(smem + SM_D + (0 * 2 + kh) * D_SZ);
    float* const DmyB = (float*)(smem + SM_D + (1 * 2 + kh) * D_SZ);

    for (int dyi = 0; dyi < NDY; dyi += 2) {
        // prefetch dy = dyi+2, dyi+3 into ring planes
        #pragma unroll
        for (int f = 2; f < 4; ++f) {
            const int dyf = dyi + f;
            const int hb = h + 2 * dyf - 20;
            if (dyf < NDY && (unsigned)hb < (unsigned)HH)
                fill_plane(sb + (uint32_t)(dyf & 3) * PLANE,
                           browset + (size_t)hb * ROWSET_B, tid);
            asm volatile("cp.async.commit_group;" ::: "memory");
        }
        asm volatile("cp.async.wait_group 2;" ::: "memory");
        __syncthreads();                       // bar1: planes dyi,dyi+1 ready; D free

        float accA0[4] = {0.f,0.f,0.f,0.f}, accA1[4] = {0.f,0.f,0.f,0.f};
        float accB0[4] = {0.f,0.f,0.f,0.f}, accB1[4] = {0.f,0.f,0.f,0.f};
        const int hbA = h + 2 * dyi - 20;
        if ((unsigned)hbA < (unsigned)HH) {
            const uint32_t bbase = sb + (uint32_t)(dyi & 3) * PLANE + boff;
            #pragma unroll
            for (int kt = 0; kt < 8; ++kt) {
                uint32_t b4[4];
                ldmx4(b4, bbase + kt * 32);
                mma_f16(accA0, ahi[kt], b4);
                mma_f16(accA0, alo[kt], b4);
                mma_f16(accA1, ahi[kt], b4 + 2);
                mma_f16(accA1, alo[kt], b4 + 2);
            }
        }
        if (dyi + 1 < NDY && (unsigned)(hbA + 2) < (unsigned)HH) {
            const uint32_t bbase = sb + (uint32_t)((dyi + 1) & 3) * PLANE + boff;
            #pragma unroll
            for (int kt = 0; kt < 8; ++kt) {
                uint32_t b4[4];
                ldmx4(b4, bbase + kt * 32);
                mma_f16(accB0, ahi[kt], b4);
                mma_f16(accB0, alo[kt], b4);
                mma_f16(accB1, ahi[kt], b4 + 2);
                mma_f16(accB1, alo[kt], b4 + 2);
            }
        }

        // store warp tiles into D[slot][kh]
        {
            const int r = lane >> 2, c = nh * 16 + (lane & 3) * 2;
            const int ro = (mh * 16 + r) * D_STRIDE + c;
            *(float2*)(DmyA + ro)                    = make_float2(accA0[0], accA0[1]);
            *(float2*)(DmyA + ro + 8 * D_STRIDE)     = make_float2(accA0[2], accA0[3]);
            *(float2*)(DmyA + ro + 8)                = make_float2(accA1[0], accA1[1]);
            *(float2*)(DmyA + ro + 8 * D_STRIDE + 8) = make_float2(accA1[2], accA1[3]);
            *(float2*)(DmyB + ro)                    = make_float2(accB0[0], accB0[1]);
            *(float2*)(DmyB + ro + 8 * D_STRIDE)     = make_float2(accB0[2], accB0[3]);
            *(float2*)(DmyB + ro + 8)                = make_float2(accB1[0], accB1[1]);
            *(float2*)(DmyB + ro + 8 * D_STRIDE + 8) = make_float2(accB1[2], accB1[3]);
        }
        __syncthreads();                       // bar2: D complete

        // epilogue (division-free): fold k-halves, band extract, write both dy
        {
            const int w2 = tid >> 3, tis = tid & 7;
            const float* Dq = (const float*)(smem + SM_D);
            float* orow = O + ((size_t)(bb * HH + h) * WW + 2 * w2 + p) * 441;
            const int row = w2 * D_STRIDE;
            #pragma unroll
            for (int j = 0; j < 3; ++j) {
                const int ti = tis + 8 * j;
                if (ti < 21) {
                    const int u2 = w2 + ti - 10;
                    float vA = 0.f, vB = 0.f;
                    if ((unsigned)u2 < 32u) {
                        vA = (Dq[row + u2] + Dq[(D_SZ/4) + row + u2]) * inv;
                        vB = (Dq[2*(D_SZ/4) + row + u2] + Dq[3*(D_SZ/4) + row + u2]) * inv;
                    }
                    orow[dyi * 21 + ti] = vA;
                    if (dyi + 1 < NDY) orow[(dyi + 1) * 21 + ti] = vB;
                }
            }
        }
        // next iteration's bar1 protects D and ring planes
    }
}

extern "C" void kernel_launch(void* const* d_in, const int* in_sizes, int n_in,
                              void* d_out, int out_size)
{
    const float* A = (const float*)d_in[0];
    const float* B = (const float*)d_in[1];
    float* O = (float*)d_out;

    static int configured = 0;
    if (!configured) {
        cudaFuncSetAttribute(corr_mma_kernel,
                             cudaFuncAttributeMaxDynamicSharedMemorySize,
                             SM_TOTAL);
        configured = 1;
    }

    convert_b_kernel<<<BATCH * HH, 256>>>(B);
    dim3 grid(HH, BATCH, 2);
    corr_mma_kernel<<<grid, 256, SM_TOTAL>>>(A, O);
}

// round 9
// speedup vs baseline: 8.4638x; 1.0315x over previous
#include <cuda_runtime.h>
#include <cstdint>

// FlowNet-C correlation cost via warp-level fp16 mma.sync, single-term.
// out[b,h,w, tj*21+ti] = (1/256) * sum_c A[b,h,w,c] * B[b, h+2tj-20, w+2ti-20, c]
// A,B: [16,48,64,256] f32. Out: [16,48,64,441] f32.
//
// CTA = (h, b, parity). Per dy: GEMM D[32 w-half, 32 u-half, K=256] in fp16
// (a_hi * b_hi, fp32 accumulate; dropped residuals ~2^-11.5 rel << 1e-3 gate).
// 8 warps = M2 x N2 x DY2: each warp owns m16 n16 FULL-K for one of the two
// dy slots -> accumulators are final. Epilogue goes registers -> gmem directly
// (predicated band extract + phantom zero fill). No D staging, no K-fold.
// A-hi fragments register-resident (64 regs). 4-plane B ring via cp.async.

#define BATCH 16
#define HH 48
#define WW 64
#define CC 256
#define NDY 21

#define RS 264                      // fp16 row stride (528B, conflict-free ldmatrix)
#define RSB (RS * 2)
#define PLANE 16896                 // 32 rows * 528B
#define ROWSET_B (2 * PLANE)        // per (b,h): parity0 hi, parity1 hi

#define SM_TOTAL (4 * PLANE)        // 67584 -> 3 CTAs/SM

// B pre-converted to fp16 hi planes
__device__ unsigned char g_B[(size_t)BATCH * HH * ROWSET_B];

// ---------------- helpers ----------------
__device__ __forceinline__ uint32_t smem_u32(const void* p) {
    uint32_t a;
    asm("{ .reg .u64 t; cvta.to.shared.u64 t, %1; cvt.u32.u64 %0, t; }"
        : "=r"(a) : "l"(p));
    return a;
}
__device__ __forceinline__ uint32_t cvt_f16x2(float x0, float x1) {
    uint32_t h;
    asm("cvt.rn.f16x2.f32 %0, %1, %2;" : "=r"(h) : "f"(x1), "f"(x0));
    return h;
}
__device__ __forceinline__ void ldmx4(uint32_t* r, uint32_t addr) {
    asm volatile("ldmatrix.sync.aligned.m8n8.x4.shared.b16 {%0,%1,%2,%3}, [%4];"
        : "=r"(r[0]), "=r"(r[1]), "=r"(r[2]), "=r"(r[3]) : "r"(addr));
}
__device__ __forceinline__ void mma_f16(float* c, const uint32_t* a, const uint32_t* b) {
    asm volatile("mma.sync.aligned.m16n8k16.row.col.f32.f16.f16.f32 "
        "{%0,%1,%2,%3}, {%4,%5,%6,%7}, {%8,%9}, {%0,%1,%2,%3};"
        : "+f"(c[0]), "+f"(c[1]), "+f"(c[2]), "+f"(c[3])
        : "r"(a[0]), "r"(a[1]), "r"(a[2]), "r"(a[3]), "r"(b[0]), "r"(b[1]));
}
__device__ __forceinline__ void cpa16(uint32_t dst, const void* src) {
    asm volatile("cp.async.cg.shared.global [%0], [%1], 16;"
                 :: "r"(dst), "l"(src) : "memory");
}
// fill one 16896B plane: 1056 chunks = 4*256 + 32
__device__ __forceinline__ void fill_plane(uint32_t dst, const unsigned char* srow, int tid) {
    #pragma unroll
    for (int j = 0; j < 4; ++j)
        cpa16(dst + (uint32_t)(tid + j * 256) * 16, srow + (size_t)(tid + j * 256) * 16);
    if (tid < 32)
        cpa16(dst + (uint32_t)(tid + 1024) * 16, srow + (size_t)(tid + 1024) * 16);
}

// ---------------- pre-pass: B fp32 -> fp16 hi planes ----------------
__global__ void convert_b_kernel(const float* __restrict__ B) {
    const int bh = blockIdx.x;                 // b*48 + h
    const float4* src = (const float4*)(B + (size_t)bh * WW * CC);
    unsigned char* dst = g_B + (size_t)bh * ROWSET_B;
    #pragma unroll
    for (int j = 0; j < 16; ++j) {
        const int id = threadIdx.x + j * 256;  // float4 id over 64x256
        const int u = id >> 6, c4 = id & 63;
        float4 v = src[id];
        uint32_t h0 = cvt_f16x2(v.x, v.y);
        uint32_t h1 = cvt_f16x2(v.z, v.w);
        const uint32_t off = (u & 1) * PLANE + (u >> 1) * RSB + c4 * 8;
        *(uint2*)(dst + off) = make_uint2(h0, h1);
    }
}

// ---------------- main kernel ----------------
__global__ __launch_bounds__(256, 3)
void corr_mma_kernel(const float* __restrict__ A, float* __restrict__ O)
{
    extern __shared__ unsigned char smem[];
    const uint32_t sb = smem_u32(smem);
    const int tid  = threadIdx.x;
    const int lane = tid & 31;
    const int wid  = tid >> 5;
    const int dyh = wid & 1;           // dy slot within the pair
    const int nh  = (wid >> 1) & 1;    // N half (16 u')
    const int mh  = (wid >> 2) & 1;    // M half (16 w')
    const int h   = blockIdx.x;
    const int bb  = blockIdx.y;
    const int p   = blockIdx.z;        // parity

    const unsigned char* const browset = g_B + (size_t)(bb * HH) * ROWSET_B + p * PLANE;

    // --- prologue prefetch: B(dy0)->plane0, B(dy1)->plane1 ---
    #pragma unroll
    for (int f = 0; f < 2; ++f) {
        const int hb = h + 2 * f - 20;
        if ((unsigned)hb < (unsigned)HH)
            fill_plane(sb + (uint32_t)f * PLANE, browset + (size_t)hb * ROWSET_B, tid);
        asm volatile("cp.async.commit_group;" ::: "memory");
    }

    // --- stage A row (this parity's 32 w) -> fp16 hi into plane 2 ---
    {
        const int w2 = tid >> 3, seg = tid & 7;    // 32 channels per seg
        const float4* asrc = (const float4*)(A
            + ((size_t)(bb * HH + h) * WW + 2 * w2 + p) * CC) + seg * 8;
        const uint32_t dsth = sb + 2 * PLANE + (uint32_t)w2 * RSB + seg * 64;
        #pragma unroll
        for (int j = 0; j < 8; ++j) {
            float4 v = asrc[j];
            uint32_t h0 = cvt_f16x2(v.x, v.y);
            uint32_t h1 = cvt_f16x2(v.z, v.w);
            asm volatile("st.shared.v2.b32 [%0], {%1,%2};"
                         :: "r"(dsth + j * 8), "r"(h0), "r"(h1) : "memory");
        }
    }
    __syncthreads();

    // --- A-hi fragments (m16 x k256) -> registers for the whole dy loop ---
    uint32_t ahi[16][4];
    {
        const uint32_t ab = sb + 2 * PLANE + (uint32_t)(mh * 16 + (lane & 15)) * RSB
                            + (lane >> 4) * 16;
        #pragma unroll
        for (int kt = 0; kt < 16; ++kt)
            ldmx4(ahi[kt], ab + kt * 32);
    }
    __syncthreads();   // planes 2,3 free for B ring after this

    // B fragment offset within a plane (x4: n16 x k16)
    const uint32_t boff = (uint32_t)(nh * 16 + ((lane >> 4) << 3) + (lane & 7)) * RSB
                          + ((lane >> 3) & 1) * 16;
    const float inv = 1.0f / 256.0f;

    for (int dyi = 0; dyi < NDY; dyi += 2) {
        // prefetch dy = dyi+2, dyi+3 into ring planes (protected by the
        // end-of-iteration barrier below)
        #pragma unroll
        for (int f = 2; f < 4; ++f) {
            const int dyf = dyi + f;
            const int hb = h + 2 * dyf - 20;
            if (dyf < NDY && (unsigned)hb < (unsigned)HH)
                fill_plane(sb + (uint32_t)(dyf & 3) * PLANE,
                           browset + (size_t)hb * ROWSET_B, tid);
            asm volatile("cp.async.commit_group;" ::: "memory");
        }
        asm volatile("cp.async.wait_group 2;" ::: "memory");
        __syncthreads();                 // planes dyi, dyi+1 ready

        const int dy = dyi + dyh;
        const int hb = h + 2 * dy - 20;

        float acc0[4] = {0.f, 0.f, 0.f, 0.f};
        float acc1[4] = {0.f, 0.f, 0.f, 0.f};
        if (dy < NDY && (unsigned)hb < (unsigned)HH) {
            const uint32_t bbase = sb + (uint32_t)(dy & 3) * PLANE + boff;
            #pragma unroll
            for (int kt = 0; kt < 16; ++kt) {
                uint32_t b4[4];
                ldmx4(b4, bbase + kt * 32);
                mma_f16(acc0, ahi[kt], b4);
                mma_f16(acc1, ahi[kt], b4 + 2);
            }
        }
        __syncthreads();                 // all LDSM done before next refill

        // epilogue: registers -> gmem, band extract + phantom zero fill
        if (dy < NDY) {
            const int R  = lane >> 2;
            const int C0 = nh * 16 + (lane & 3) * 2;
            float* const obase = O + ((size_t)(bb * HH + h) * WW + p) * 441
                                 + (size_t)dy * 21;
            #pragma unroll
            for (int rr = 0; rr < 2; ++rr) {
                const int w2 = mh * 16 + R + rr * 8;
                float* orow = obase + (size_t)w2 * 882;   // w = 2*w2+p
                #pragma unroll
                for (int cg = 0; cg < 2; ++cg) {
                    const int ti = C0 + cg * 8 - w2 + 10;
                    const float v0 = (cg ? acc1 : acc0)[rr * 2 + 0] * inv;
                    const float v1 = (cg ? acc1 : acc0)[rr * 2 + 1] * inv;
                    if ((unsigned)ti < 21u)       orow[ti]     = v0;
                    if ((unsigned)(ti + 1) < 21u) orow[ti + 1] = v1;
                }
                // phantom zeros (u out of [0,W)): nh0 -> left band, nh1 -> right
                if ((lane & 3) == 0) {
                    if (nh == 0) {
                        const int nz = 10 - w2;
                        for (int j = 0; j < nz; ++j) orow[j] = 0.0f;
                    } else {
                        const int nz = w2 - 21;
                        for (int j = 0; j < nz; ++j) orow[20 - j] = 0.0f;
                    }
                }
            }
        }
    }
}

extern "C" void kernel_launch(void* const* d_in, const int* in_sizes, int n_in,
                              void* d_out, int out_size)
{
    const float* A = (const float*)d_in[0];
    const float* B = (const float*)d_in[1];
    float* O = (float*)d_out;

    static int configured = 0;
    if (!configured) {
        cudaFuncSetAttribute(corr_mma_kernel,
                             cudaFuncAttributeMaxDynamicSharedMemorySize,
                             SM_TOTAL);
        configured = 1;
    }

    convert_b_kernel<<<BATCH * HH, 256>>>(B);
    dim3 grid(HH, BATCH, 2);
    corr_mma_kernel<<<grid, 256, SM_TOTAL>>>(A, O);
}